// round 9
// baseline (speedup 1.0000x reference)
#include <cuda_runtime.h>
#include <cuda_bf16.h>
#include <cstdint>

// Problem sizes (fixed by the reference)
#define NN   8192
#define DIN  512
#define DOUT 512

// ---------------- scratch (device globals; no allocation allowed) ----------------
__device__ __align__(256) float g_Wh[(size_t)NN * DOUT];        // 16 MB
__device__ __align__(256) float g_P[(size_t)NN * NN];           // 268 MB
__device__ __align__(16)  float g_s1[NN], g_s2[NN];
__device__ __align__(16)  float g_E1p[NN], g_E1n[NN], g_E2p[NN], g_E2n[NN];
__device__ __align__(16)  float g_invZ[NN];

// ---------------- tf32 helpers ----------------
__device__ __forceinline__ uint32_t f32_to_tf32(float x) {
    uint32_t r;
    asm("cvt.rna.tf32.f32 %0, %1;" : "=r"(r) : "f"(x));
    return r;
}

__device__ __forceinline__ void mma_tf32(float c[4], const uint32_t a[4], const uint32_t b[2]) {
    asm volatile(
        "mma.sync.aligned.m16n8k8.row.col.f32.tf32.tf32.f32 "
        "{%0,%1,%2,%3}, {%4,%5,%6,%7}, {%8,%9}, {%0,%1,%2,%3};\n"
        : "+f"(c[0]), "+f"(c[1]), "+f"(c[2]), "+f"(c[3])
        : "r"(a[0]), "r"(a[1]), "r"(a[2]), "r"(a[3]),
          "r"(b[0]), "r"(b[1]));
}

__device__ __forceinline__ void cp_async16(void* smem_ptr, const void* gmem_ptr) {
    uint32_t s = (uint32_t)__cvta_generic_to_shared(smem_ptr);
    asm volatile("cp.async.cg.shared.global [%0], [%1], 16;\n" :: "r"(s), "l"(gmem_ptr));
}
__device__ __forceinline__ void cp_async_commit() { asm volatile("cp.async.commit_group;\n"); }

// ---------------- GEMM: C[M,N] = A[M,K] @ B[K,N] (both row-major) ----------------
// epilogue: C = acc * rowscale[row] + bias[col]   (either may be null)
// BM=128, BN=256, BK=32, 512 threads (16 warps as 4x4), warp tile 32x64.
#define BM 128
#define BN 256
#define BK 32
#define LDA_S 36    // BK+4  -> fragment A loads conflict-free (36 mod 32 = 4; 4*gid+tig = lane)
#define LDB_S 264   // BN+8  -> fragment B loads conflict-free (264 mod 32 = 8; 8*tig+gid unique)
#define GEMM_SMEM_BYTES ((2 * BM * LDA_S + 2 * BK * LDB_S) * 4)   // 104448

__global__ void __launch_bounds__(512, 1)
gemm_tf32_kernel(const float* __restrict__ A, const float* __restrict__ B,
                 float* __restrict__ C, int M, int Nn, int K,
                 const float* __restrict__ bias, const float* __restrict__ rowscale)
{
    extern __shared__ float smem[];
    float* As0 = smem;
    float* As1 = smem + BM * LDA_S;
    float* Bs0 = smem + 2 * BM * LDA_S;
    float* Bs1 = Bs0 + BK * LDB_S;
    float* AsBuf[2] = { As0, As1 };
    float* BsBuf[2] = { Bs0, Bs1 };

    const int tid  = threadIdx.x;
    const int warp = tid >> 5;
    const int lane = tid & 31;
    const int warpRow = warp >> 2;   // 0..3
    const int warpCol = warp & 3;    // 0..3
    const int gid = lane >> 2;       // 0..7
    const int tig = lane & 3;        // 0..3

    const size_t aBase = (size_t)blockIdx.y * BM * (size_t)K;
    const size_t bBase = (size_t)blockIdx.x * BN;

    // global -> smem load mapping
    const int aRow = tid >> 3;          // 0..63 (and +64)
    const int aCol = (tid & 7) * 4;     // 0,4,...,28
    const int bRow = tid >> 6;          // 0..7 (and +8,+16,+24)
    const int bCol = (tid & 63) * 4;    // 0..252

    auto loadTile = [&](int kt, int buf) {
        const size_t k0 = (size_t)kt * BK;
        const float* Ag = A + aBase + k0;
        cp_async16(&AsBuf[buf][aRow * LDA_S + aCol],        Ag + (size_t)aRow * K + aCol);
        cp_async16(&AsBuf[buf][(aRow + 64) * LDA_S + aCol], Ag + (size_t)(aRow + 64) * K + aCol);
        const float* Bg = B + k0 * (size_t)Nn + bBase;
        #pragma unroll
        for (int r = 0; r < 4; r++)
            cp_async16(&BsBuf[buf][(bRow + r * 8) * LDB_S + bCol],
                       Bg + (size_t)(bRow + r * 8) * Nn + bCol);
        cp_async_commit();
    };

    float acc[2][8][4];
    #pragma unroll
    for (int m = 0; m < 2; m++)
        #pragma unroll
        for (int n = 0; n < 8; n++)
            #pragma unroll
            for (int q = 0; q < 4; q++)
                acc[m][n][q] = 0.0f;

    const int KT = K / BK;
    loadTile(0, 0);

    for (int kt = 0; kt < KT; kt++) {
        const int buf = kt & 1;
        if (kt + 1 < KT) {
            loadTile(kt + 1, buf ^ 1);
            asm volatile("cp.async.wait_group 1;\n");
        } else {
            asm volatile("cp.async.wait_group 0;\n");
        }
        __syncthreads();

        const float* Asb = AsBuf[buf];
        const float* Bsb = BsBuf[buf];

        #pragma unroll
        for (int s = 0; s < 4; s++) {
            const int kk = s * 8;
            uint32_t af[2][4];
            uint32_t bf[8][2];
            #pragma unroll
            for (int m = 0; m < 2; m++) {
                const int rb = warpRow * 32 + m * 16;
                af[m][0] = f32_to_tf32(Asb[(rb + gid)     * LDA_S + kk + tig]);
                af[m][1] = f32_to_tf32(Asb[(rb + gid + 8) * LDA_S + kk + tig]);
                af[m][2] = f32_to_tf32(Asb[(rb + gid)     * LDA_S + kk + tig + 4]);
                af[m][3] = f32_to_tf32(Asb[(rb + gid + 8) * LDA_S + kk + tig + 4]);
            }
            #pragma unroll
            for (int n = 0; n < 8; n++) {
                const int cb = warpCol * 64 + n * 8;
                bf[n][0] = f32_to_tf32(Bsb[(kk + tig)     * LDB_S + cb + gid]);
                bf[n][1] = f32_to_tf32(Bsb[(kk + tig + 4) * LDB_S + cb + gid]);
            }
            #pragma unroll
            for (int m = 0; m < 2; m++)
                #pragma unroll
                for (int n = 0; n < 8; n++)
                    mma_tf32(acc[m][n], af[m], bf[n]);
        }
        __syncthreads();
    }

    // epilogue
    #pragma unroll
    for (int m = 0; m < 2; m++) {
        const int r0 = blockIdx.y * BM + warpRow * 32 + m * 16 + gid;
        const int r1 = r0 + 8;
        const float rs0 = rowscale ? rowscale[r0] : 1.0f;
        const float rs1 = rowscale ? rowscale[r1] : 1.0f;
        #pragma unroll
        for (int n = 0; n < 8; n++) {
            const int c0 = blockIdx.x * BN + warpCol * 64 + n * 8 + tig * 2;
            const float bv0 = bias ? bias[c0]     : 0.0f;
            const float bv1 = bias ? bias[c0 + 1] : 0.0f;
            float2 v0 = make_float2(acc[m][n][0] * rs0 + bv0, acc[m][n][1] * rs0 + bv1);
            float2 v1 = make_float2(acc[m][n][2] * rs1 + bv0, acc[m][n][3] * rs1 + bv1);
            *(float2*)&C[(size_t)r0 * Nn + c0] = v0;
            *(float2*)&C[(size_t)r1 * Nn + c0] = v1;
        }
    }
}

// ---------------- per-node scores + exp factors ----------------
// one warp per row; s1 = Wh[i]·a1 + b1, s2 = Wh[i]·a2 + b2
__global__ void score_kernel(const float* __restrict__ a1, const float* __restrict__ a2,
                             const float* __restrict__ b1p, const float* __restrict__ b2p)
{
    const int warp = threadIdx.x >> 5;
    const int lane = threadIdx.x & 31;
    const int row  = blockIdx.x * 8 + warp;
    const float* w = g_Wh + (size_t)row * DOUT;

    float d1 = 0.0f, d2 = 0.0f;
    #pragma unroll
    for (int c = lane; c < DOUT; c += 32) {
        const float v = w[c];
        d1 += v * a1[c];
        d2 += v * a2[c];
    }
    #pragma unroll
    for (int o = 16; o > 0; o >>= 1) {
        d1 += __shfl_xor_sync(0xffffffffu, d1, o);
        d2 += __shfl_xor_sync(0xffffffffu, d2, o);
    }
    if (lane == 0) {
        const float v1 = d1 + b1p[0];
        const float v2 = d2 + b2p[0];
        g_s1[row] = v1;  g_s2[row] = v2;
        g_E1p[row] = expf(v1);         g_E1n[row] = expf(0.2f * v1);
        g_E2p[row] = expf(v2);         g_E2n[row] = expf(0.2f * v2);
    }
}

// ---------------- P generation + deterministic row-sum ----------------
// P[i][j] = adj ? (s1_i+s2_j > 0 ? e^{s1_i} e^{s2_j} : e^{0.2 s1_i} e^{0.2 s2_j}) : 0
__global__ void pgen_kernel(const int* __restrict__ adj)
{
    const int i = blockIdx.x;
    const int4*   arow = (const int4*)  (adj + (size_t)i * NN);
    float4*       prow = (float4*)      (g_P + (size_t)i * NN);
    const float4* s2v4 = (const float4*)g_s2;
    const float4* e2p4 = (const float4*)g_E2p;
    const float4* e2n4 = (const float4*)g_E2n;

    const float s1i = g_s1[i];
    const float e1p = g_E1p[i];
    const float e1n = g_E1n[i];

    float lsum = 0.0f;
    for (int j4 = threadIdx.x; j4 < NN / 4; j4 += 256) {
        const int4   a  = arow[j4];
        const float4 s2 = s2v4[j4];
        const float4 p2 = e2p4[j4];
        const float4 n2 = e2n4[j4];
        float4 o;
        o.x = (a.x > 0) ? ((s1i + s2.x > 0.0f) ? e1p * p2.x : e1n * n2.x) : 0.0f;
        o.y = (a.y > 0) ? ((s1i + s2.y > 0.0f) ? e1p * p2.y : e1n * n2.y) : 0.0f;
        o.z = (a.z > 0) ? ((s1i + s2.z > 0.0f) ? e1p * p2.z : e1n * n2.z) : 0.0f;
        o.w = (a.w > 0) ? ((s1i + s2.w > 0.0f) ? e1p * p2.w : e1n * n2.w) : 0.0f;
        lsum += (o.x + o.y) + (o.z + o.w);
        prow[j4] = o;
    }

    __shared__ float red[256];
    red[threadIdx.x] = lsum;
    __syncthreads();
    #pragma unroll
    for (int s = 128; s > 0; s >>= 1) {
        if (threadIdx.x < s) red[threadIdx.x] += red[threadIdx.x + s];
        __syncthreads();
    }
    if (threadIdx.x == 0) g_invZ[i] = 1.0f / red[0];
}

// ---------------- launch ----------------
extern "C" void kernel_launch(void* const* d_in, const int* in_sizes, int n_in,
                              void* d_out, int out_size)
{
    const float* h   = (const float*)d_in[0];
    const int*   adj = (const int*)  d_in[1];
    const float* W   = (const float*)d_in[2];
    const float* bW  = (const float*)d_in[3];
    const float* a1  = (const float*)d_in[4];
    const float* b1  = (const float*)d_in[5];
    const float* a2  = (const float*)d_in[6];
    const float* b2  = (const float*)d_in[7];
    float* out = (float*)d_out;

    cudaFuncSetAttribute(gemm_tf32_kernel,
                         cudaFuncAttributeMaxDynamicSharedMemorySize, GEMM_SMEM_BYTES);

    void *pWh, *pP, *pInvZ;
    cudaGetSymbolAddress(&pWh,   g_Wh);
    cudaGetSymbolAddress(&pP,    g_P);
    cudaGetSymbolAddress(&pInvZ, g_invZ);

    // 1) Wh = h @ W + bW        [8192,512] = [8192,512]@[512,512]
    {
        dim3 grid(DOUT / BN, NN / BM);
        gemm_tf32_kernel<<<grid, 512, GEMM_SMEM_BYTES>>>(
            h, W, (float*)pWh, NN, DOUT, DIN, bW, nullptr);
    }

    // 2) scores s1,s2 and exp factors
    score_kernel<<<NN / 8, 256>>>(a1, a2, b1, b2);

    // 3) P matrix + 1/Z per row (deterministic per-row reduction, no atomics)
    pgen_kernel<<<NN, 256>>>(adj);

    // 4) out = (P @ Wh) * invZ[row]     [8192,512] = [8192,8192]@[8192,512]
    {
        dim3 grid(DOUT / BN, NN / BM);
        gemm_tf32_kernel<<<grid, 512, GEMM_SMEM_BYTES>>>(
            (const float*)pP, (const float*)pWh, out, NN, DOUT, NN, nullptr,
            (const float*)pInvZ);
    }
}

// round 13
// speedup vs baseline: 1.2309x; 1.2309x over previous
#include <cuda_runtime.h>
#include <cstdint>

#define NN   8192
#define DIN  512
#define DOUT 512

// ---------------- scratch (device globals; no allocation allowed) ----------------
__device__ __align__(256) float g_Wh[(size_t)NN * DOUT];    // 16 MB exact (for scores)
__device__ __align__(256) float g_WhR[(size_t)NN * DOUT];   // 16 MB rna-rounded to tf32
__device__ __align__(256) float g_P[(size_t)NN * NN];       // 268 MB (rna-rounded to tf32)
__device__ __align__(16) float g_s1[NN], g_s2[NN];
__device__ __align__(16) float g_E1p[NN], g_E1n[NN], g_E2p[NN], g_E2n[NN];
__device__ __align__(16) float g_invZ[NN];

// ---------------- helpers ----------------
__device__ __forceinline__ uint32_t rna_tf32(float x) {
    uint32_t r;
    asm("cvt.rna.tf32.f32 %0, %1;" : "=r"(r) : "f"(x));
    return r;
}

__device__ __forceinline__ void mma_tf32(float c[4], const uint32_t a[4], const uint32_t b[2]) {
    asm volatile(
        "mma.sync.aligned.m16n8k8.row.col.f32.tf32.tf32.f32 "
        "{%0,%1,%2,%3}, {%4,%5,%6,%7}, {%8,%9}, {%0,%1,%2,%3};\n"
        : "+f"(c[0]), "+f"(c[1]), "+f"(c[2]), "+f"(c[3])
        : "r"(a[0]), "r"(a[1]), "r"(a[2]), "r"(a[3]),
          "r"(b[0]), "r"(b[1]));
}

__device__ __forceinline__ void cp_async16(void* smem_ptr, const void* gmem_ptr) {
    uint32_t s = (uint32_t)__cvta_generic_to_shared(smem_ptr);
    asm volatile("cp.async.cg.shared.global [%0], [%1], 16;\n" :: "r"(s), "l"(gmem_ptr));
}
__device__ __forceinline__ void cp_async_commit() { asm volatile("cp.async.commit_group;\n"); }

// ---------------- GEMM: C[M,N] = A[M,K] @ B[K,N] (both row-major) ----------------
// DO_CVT=true : per-fragment cvt.rna (use for GEMM1 whose inputs are raw fp32)
// DO_CVT=false: raw bits into the MMA — REQUIRES inputs pre-rounded to tf32 (rna),
//               which makes it bit-identical to the DO_CVT path at zero ALU cost.
// epilogue: C = acc * rowscale[row] + bias[col]; optionally also writes
//           C2 = rna_tf32(C) (rounded copy, used by GEMM1 to produce g_WhR).
#define BM 128
#define BN 128
#define BK 32
#define LDA_S 36    // BK+4  -> A fragment loads conflict-free
#define LDB_S 136   // BN+8  -> B fragment loads conflict-free
#define GEMM_SMEM_BYTES ((2 * BM * LDA_S + 2 * BK * LDB_S) * 4)   // 71680

template <bool DO_CVT>
__global__ void __launch_bounds__(256, 2)
gemm_tf32_kernel(const float* __restrict__ A, const float* __restrict__ B,
                 float* __restrict__ C, float* __restrict__ C2,
                 int M, int Nn, int K,
                 const float* __restrict__ bias, const float* __restrict__ rowscale)
{
    extern __shared__ float smem[];
    float* AsBuf[2] = { smem, smem + BM * LDA_S };
    float* Bs0 = smem + 2 * BM * LDA_S;
    float* BsBuf[2] = { Bs0, Bs0 + BK * LDB_S };

    const int tid  = threadIdx.x;
    const int warp = tid >> 5;
    const int lane = tid & 31;
    const int warpRow = warp >> 1;   // 0..3
    const int warpCol = warp & 1;    // 0..1
    const int gid = lane >> 2;       // 0..7
    const int tig = lane & 3;        // 0..3

    const size_t aBase = (size_t)blockIdx.y * BM * (size_t)K;
    const size_t bBase = (size_t)blockIdx.x * BN;

    const int aRow = tid >> 3;          // 0..31 (+32,+64,+96)
    const int aCol = (tid & 7) * 4;
    const int bRow = tid >> 5;          // 0..7  (+8,+16,+24)
    const int bCol = (tid & 31) * 4;

    auto loadTile = [&](int kt, int buf) {
        const size_t k0 = (size_t)kt * BK;
        const float* Ag = A + aBase + k0;
        #pragma unroll
        for (int r = 0; r < 4; r++)
            cp_async16(&AsBuf[buf][(aRow + r * 32) * LDA_S + aCol],
                       Ag + (size_t)(aRow + r * 32) * K + aCol);
        const float* Bg = B + k0 * (size_t)Nn + bBase;
        #pragma unroll
        for (int r = 0; r < 4; r++)
            cp_async16(&BsBuf[buf][(bRow + r * 8) * LDB_S + bCol],
                       Bg + (size_t)(bRow + r * 8) * Nn + bCol);
        cp_async_commit();
    };

    float acc[2][8][4];
    #pragma unroll
    for (int m = 0; m < 2; m++)
        #pragma unroll
        for (int n = 0; n < 8; n++)
            #pragma unroll
            for (int q = 0; q < 4; q++)
                acc[m][n][q] = 0.0f;

    const int KT = K / BK;
    loadTile(0, 0);

    for (int kt = 0; kt < KT; kt++) {
        const int buf = kt & 1;
        if (kt + 1 < KT) {
            loadTile(kt + 1, buf ^ 1);
            asm volatile("cp.async.wait_group 1;\n" ::: "memory");
        } else {
            asm volatile("cp.async.wait_group 0;\n" ::: "memory");
        }
        __syncthreads();

        const float* Asb = AsBuf[buf];
        const float* Bsb = BsBuf[buf];

        #pragma unroll
        for (int s = 0; s < 4; s++) {
            const int kk = s * 8;
            uint32_t af[2][4];
            uint32_t bf[8][2];
            #pragma unroll
            for (int m = 0; m < 2; m++) {
                const int rb = warpRow * 32 + m * 16;
                float v0 = Asb[(rb + gid)     * LDA_S + kk + tig];
                float v1 = Asb[(rb + gid + 8) * LDA_S + kk + tig];
                float v2 = Asb[(rb + gid)     * LDA_S + kk + tig + 4];
                float v3 = Asb[(rb + gid + 8) * LDA_S + kk + tig + 4];
                if (DO_CVT) {
                    af[m][0] = rna_tf32(v0); af[m][1] = rna_tf32(v1);
                    af[m][2] = rna_tf32(v2); af[m][3] = rna_tf32(v3);
                } else {
                    af[m][0] = __float_as_uint(v0); af[m][1] = __float_as_uint(v1);
                    af[m][2] = __float_as_uint(v2); af[m][3] = __float_as_uint(v3);
                }
            }
            #pragma unroll
            for (int n = 0; n < 8; n++) {
                const int cb = warpCol * 64 + n * 8;
                float w0 = Bsb[(kk + tig)     * LDB_S + cb + gid];
                float w1 = Bsb[(kk + tig + 4) * LDB_S + cb + gid];
                if (DO_CVT) {
                    bf[n][0] = rna_tf32(w0); bf[n][1] = rna_tf32(w1);
                } else {
                    bf[n][0] = __float_as_uint(w0); bf[n][1] = __float_as_uint(w1);
                }
            }
            #pragma unroll
            for (int m = 0; m < 2; m++)
                #pragma unroll
                for (int n = 0; n < 8; n++)
                    mma_tf32(acc[m][n], af[m], bf[n]);
        }
        __syncthreads();
    }

    // epilogue
    #pragma unroll
    for (int m = 0; m < 2; m++) {
        const int r0 = blockIdx.y * BM + warpRow * 32 + m * 16 + gid;
        const int r1 = r0 + 8;
        const float rs0 = rowscale ? rowscale[r0] : 1.0f;
        const float rs1 = rowscale ? rowscale[r1] : 1.0f;
        #pragma unroll
        for (int n = 0; n < 8; n++) {
            const int c0 = blockIdx.x * BN + warpCol * 64 + n * 8 + tig * 2;
            const float bv0 = bias ? bias[c0]     : 0.0f;
            const float bv1 = bias ? bias[c0 + 1] : 0.0f;
            float2 v0 = make_float2(acc[m][n][0] * rs0 + bv0, acc[m][n][1] * rs0 + bv1);
            float2 v1 = make_float2(acc[m][n][2] * rs1 + bv0, acc[m][n][3] * rs1 + bv1);
            *(float2*)&C[(size_t)r0 * Nn + c0] = v0;
            *(float2*)&C[(size_t)r1 * Nn + c0] = v1;
            if (C2) {
                float2 u0 = make_float2(__uint_as_float(rna_tf32(v0.x)),
                                        __uint_as_float(rna_tf32(v0.y)));
                float2 u1 = make_float2(__uint_as_float(rna_tf32(v1.x)),
                                        __uint_as_float(rna_tf32(v1.y)));
                *(float2*)&C2[(size_t)r0 * Nn + c0] = u0;
                *(float2*)&C2[(size_t)r1 * Nn + c0] = u1;
            }
        }
    }
}

// ---------------- per-node scores + exp factors (uses exact g_Wh) ----------------
__global__ void score_kernel(const float* __restrict__ a1, const float* __restrict__ a2,
                             const float* __restrict__ b1p, const float* __restrict__ b2p)
{
    const int warp = threadIdx.x >> 5;
    const int lane = threadIdx.x & 31;
    const int row  = blockIdx.x * 8 + warp;
    const float* w = g_Wh + (size_t)row * DOUT;

    float d1 = 0.0f, d2 = 0.0f;
    #pragma unroll
    for (int c = lane; c < DOUT; c += 32) {
        const float v = w[c];
        d1 += v * a1[c];
        d2 += v * a2[c];
    }
    #pragma unroll
    for (int o = 16; o > 0; o >>= 1) {
        d1 += __shfl_xor_sync(0xffffffffu, d1, o);
        d2 += __shfl_xor_sync(0xffffffffu, d2, o);
    }
    if (lane == 0) {
        const float v1 = d1 + b1p[0];
        const float v2 = d2 + b2p[0];
        g_s1[row] = v1;  g_s2[row] = v2;
        g_E1p[row] = expf(v1);         g_E1n[row] = expf(0.2f * v1);
        g_E2p[row] = expf(v2);         g_E2n[row] = expf(0.2f * v2);
    }
}

// ---------------- P generation (rna-rounded to tf32) + row-sum ----------------
__global__ void pgen_kernel(const int* __restrict__ adj)
{
    const int i = blockIdx.x;
    const int4*   arow = (const int4*)  (adj + (size_t)i * NN);
    float4*       prow = (float4*)      (g_P + (size_t)i * NN);
    const float4* s2v4 = (const float4*)g_s2;
    const float4* e2p4 = (const float4*)g_E2p;
    const float4* e2n4 = (const float4*)g_E2n;

    const float s1i = g_s1[i];
    const float e1p = g_E1p[i];
    const float e1n = g_E1n[i];

    float lsum = 0.0f;
    for (int j4 = threadIdx.x; j4 < NN / 4; j4 += 256) {
        const int4   a  = arow[j4];
        const float4 s2 = s2v4[j4];
        const float4 p2 = e2p4[j4];
        const float4 n2 = e2n4[j4];
        float4 o;
        o.x = (a.x > 0) ? ((s1i + s2.x > 0.0f) ? e1p * p2.x : e1n * n2.x) : 0.0f;
        o.y = (a.y > 0) ? ((s1i + s2.y > 0.0f) ? e1p * p2.y : e1n * n2.y) : 0.0f;
        o.z = (a.z > 0) ? ((s1i + s2.z > 0.0f) ? e1p * p2.z : e1n * n2.z) : 0.0f;
        o.w = (a.w > 0) ? ((s1i + s2.w > 0.0f) ? e1p * p2.w : e1n * n2.w) : 0.0f;
        // round to tf32 (rna) so GEMM2 can feed raw bits to the MMA
        o.x = __uint_as_float(rna_tf32(o.x));
        o.y = __uint_as_float(rna_tf32(o.y));
        o.z = __uint_as_float(rna_tf32(o.z));
        o.w = __uint_as_float(rna_tf32(o.w));
        lsum += (o.x + o.y) + (o.z + o.w);
        prow[j4] = o;
    }

    __shared__ float red[256];
    red[threadIdx.x] = lsum;
    __syncthreads();
    #pragma unroll
    for (int s = 128; s > 0; s >>= 1) {
        if (threadIdx.x < s) red[threadIdx.x] += red[threadIdx.x + s];
        __syncthreads();
    }
    if (threadIdx.x == 0) g_invZ[i] = 1.0f / red[0];
}

// ---------------- launch ----------------
extern "C" void kernel_launch(void* const* d_in, const int* in_sizes, int n_in,
                              void* d_out, int out_size)
{
    const float* h   = (const float*)d_in[0];
    const int*   adj = (const int*)  d_in[1];
    const float* W   = (const float*)d_in[2];
    const float* bW  = (const float*)d_in[3];
    const float* a1  = (const float*)d_in[4];
    const float* b1  = (const float*)d_in[5];
    const float* a2  = (const float*)d_in[6];
    const float* b2  = (const float*)d_in[7];
    float* out = (float*)d_out;

    cudaFuncSetAttribute(gemm_tf32_kernel<true>,
                         cudaFuncAttributeMaxDynamicSharedMemorySize, GEMM_SMEM_BYTES);
    cudaFuncSetAttribute(gemm_tf32_kernel<false>,
                         cudaFuncAttributeMaxDynamicSharedMemorySize, GEMM_SMEM_BYTES);

    void *pWh, *pWhR, *pP, *pInvZ;
    cudaGetSymbolAddress(&pWh,   g_Wh);
    cudaGetSymbolAddress(&pWhR,  g_WhR);
    cudaGetSymbolAddress(&pP,    g_P);
    cudaGetSymbolAddress(&pInvZ, g_invZ);

    // 1) Wh = h @ W + bW  (with per-fragment rna cvt); also writes WhR = rna(Wh)
    {
        dim3 grid(DOUT / BN, NN / BM);
        gemm_tf32_kernel<true><<<grid, 256, GEMM_SMEM_BYTES>>>(
            h, W, (float*)pWh, (float*)pWhR, NN, DOUT, DIN, bW, nullptr);
    }

    // 2) scores s1,s2 and exp factors (exact Wh)
    score_kernel<<<NN / 8, 256>>>(a1, a2, b1, b2);

    // 3) P matrix (tf32-rounded) + 1/Z per row
    pgen_kernel<<<NN, 256>>>(adj);

    // 4) out = (P @ WhR) * invZ[row]  — raw-bit MMA on pre-rounded operands
    {
        dim3 grid(DOUT / BN, NN / BM);
        gemm_tf32_kernel<false><<<grid, 256, GEMM_SMEM_BYTES>>>(
            (const float*)pP, (const float*)pWhR, out, nullptr, NN, DOUT, NN, nullptr,
            (const float*)pInvZ);
    }
}

// round 14
// speedup vs baseline: 1.3770x; 1.1187x over previous
#include <cuda_runtime.h>
#include <cstdint>

#define NN   8192
#define DIN  512
#define DOUT 512

// ---------------- scratch (device globals; no allocation allowed) ----------------
__device__ __align__(256) float g_Wh[(size_t)NN * DOUT];    // 16 MB exact (for scores)
__device__ __align__(256) float g_WhR[(size_t)NN * DOUT];   // 16 MB rna-rounded to tf32
__device__ __align__(256) float g_P[(size_t)NN * NN];       // 268 MB (rna-rounded to tf32)
__device__ __align__(16) float g_s1[NN], g_s2[NN];
__device__ __align__(16) float g_E1p[NN], g_E1n[NN], g_E2p[NN], g_E2n[NN];
__device__ __align__(16) float g_invZ[NN];

// ---------------- helpers ----------------
__device__ __forceinline__ uint32_t rna_tf32(float x) {
    uint32_t r;
    asm("cvt.rna.tf32.f32 %0, %1;" : "=r"(r) : "f"(x));
    return r;
}

__device__ __forceinline__ void mma_tf32(float c[4], const uint32_t a[4], const uint32_t b[2]) {
    asm volatile(
        "mma.sync.aligned.m16n8k8.row.col.f32.tf32.tf32.f32 "
        "{%0,%1,%2,%3}, {%4,%5,%6,%7}, {%8,%9}, {%0,%1,%2,%3};\n"
        : "+f"(c[0]), "+f"(c[1]), "+f"(c[2]), "+f"(c[3])
        : "r"(a[0]), "r"(a[1]), "r"(a[2]), "r"(a[3]),
          "r"(b[0]), "r"(b[1]));
}

__device__ __forceinline__ void cp_async16(void* smem_ptr, const void* gmem_ptr) {
    uint32_t s = (uint32_t)__cvta_generic_to_shared(smem_ptr);
    asm volatile("cp.async.cg.shared.global [%0], [%1], 16;\n" :: "r"(s), "l"(gmem_ptr));
}
__device__ __forceinline__ void cp_async_commit() { asm volatile("cp.async.commit_group;\n"); }

// ---------------- GEMM: C[M,N] = A[M,K] @ B[K,N] (both row-major) ----------------
// BM=128, BN=256, BK=32, 256 threads = 8 warps as 2x4, warp tile 64x64.
// 3-stage cp.async pipeline, ONE __syncthreads per k-iter (valid with >=3 stages:
// the buffer refilled at iter kt was last read at iter kt-1, and every warp is
// past that read when it crosses this iter's barrier).
// DO_CVT=true : per-fragment cvt.rna (GEMM1, raw fp32 inputs)
// DO_CVT=false: raw bits into MMA — requires operands pre-rounded to tf32 (rna).
#define BM 128
#define BN 256
#define BK 32
#define NSTG 3
#define LDA_S 36    // BK+4  -> A fragment loads conflict-free
#define LDB_S 264   // BN+8  -> B fragment loads conflict-free
#define STG_FLOATS (BM * LDA_S + BK * LDB_S)              // 13056
#define GEMM_SMEM_BYTES (NSTG * STG_FLOATS * 4)           // 156672

template <bool DO_CVT>
__global__ void __launch_bounds__(256, 1)
gemm_tf32_kernel(const float* __restrict__ A, const float* __restrict__ B,
                 float* __restrict__ C, float* __restrict__ C2,
                 int M, int Nn, int K,
                 const float* __restrict__ bias, const float* __restrict__ rowscale)
{
    extern __shared__ float smem[];

    const int tid  = threadIdx.x;
    const int warp = tid >> 5;
    const int lane = tid & 31;
    const int warpRow = warp >> 2;   // 0..1  (64-row slice)
    const int warpCol = warp & 3;    // 0..3  (64-col slice)
    const int gid = lane >> 2;       // 0..7
    const int tig = lane & 3;        // 0..3

    const size_t aBase = (size_t)blockIdx.y * BM * (size_t)K;
    const size_t bBase = (size_t)blockIdx.x * BN;

    // global -> smem staging (float4 per thread)
    const int aRow = tid >> 3;          // 0..31 (+32,+64,+96)
    const int aCol = (tid & 7) * 4;     // 0..28
    const int bRow = tid >> 6;          // 0..3  (+4,+8,...,+28)
    const int bCol = (tid & 63) * 4;    // 0..252

    auto loadTile = [&](int kt, int buf) {
        float* As = smem + buf * STG_FLOATS;
        float* Bs = As + BM * LDA_S;
        const size_t k0 = (size_t)kt * BK;
        const float* Ag = A + aBase + k0;
        #pragma unroll
        for (int r = 0; r < 4; r++)
            cp_async16(&As[(aRow + r * 32) * LDA_S + aCol],
                       Ag + (size_t)(aRow + r * 32) * K + aCol);
        const float* Bg = B + k0 * (size_t)Nn + bBase;
        #pragma unroll
        for (int r = 0; r < 8; r++)
            cp_async16(&Bs[(bRow + r * 4) * LDB_S + bCol],
                       Bg + (size_t)(bRow + r * 4) * Nn + bCol);
        cp_async_commit();
    };

    float acc[4][8][4];
    #pragma unroll
    for (int m = 0; m < 4; m++)
        #pragma unroll
        for (int n = 0; n < 8; n++)
            #pragma unroll
            for (int q = 0; q < 4; q++)
                acc[m][n][q] = 0.0f;

    const int KT = K / BK;
    loadTile(0, 0);
    loadTile(1, 1);

    int buf = 0;
    for (int kt = 0; kt < KT; kt++) {
        if (kt + 1 < KT) asm volatile("cp.async.wait_group 1;\n" ::: "memory");
        else             asm volatile("cp.async.wait_group 0;\n" ::: "memory");
        __syncthreads();

        if (kt + 2 < KT) {
            int lb = buf + 2; if (lb >= NSTG) lb -= NSTG;
            loadTile(kt + 2, lb);
        }

        const float* Asb = smem + buf * STG_FLOATS;
        const float* Bsb = Asb + BM * LDA_S;
        const int rbase = warpRow * 64;
        const int cbase = warpCol * 64;

        #pragma unroll
        for (int s = 0; s < 4; s++) {
            const int kk = s * 8;
            uint32_t af[4][4];
            uint32_t bf[8][2];
            #pragma unroll
            for (int m = 0; m < 4; m++) {
                const int rb = rbase + m * 16;
                float v0 = Asb[(rb + gid)     * LDA_S + kk + tig];
                float v1 = Asb[(rb + gid + 8) * LDA_S + kk + tig];
                float v2 = Asb[(rb + gid)     * LDA_S + kk + tig + 4];
                float v3 = Asb[(rb + gid + 8) * LDA_S + kk + tig + 4];
                if (DO_CVT) {
                    af[m][0] = rna_tf32(v0); af[m][1] = rna_tf32(v1);
                    af[m][2] = rna_tf32(v2); af[m][3] = rna_tf32(v3);
                } else {
                    af[m][0] = __float_as_uint(v0); af[m][1] = __float_as_uint(v1);
                    af[m][2] = __float_as_uint(v2); af[m][3] = __float_as_uint(v3);
                }
            }
            #pragma unroll
            for (int n = 0; n < 8; n++) {
                const int cb = cbase + n * 8;
                float w0 = Bsb[(kk + tig)     * LDB_S + cb + gid];
                float w1 = Bsb[(kk + tig + 4) * LDB_S + cb + gid];
                if (DO_CVT) {
                    bf[n][0] = rna_tf32(w0); bf[n][1] = rna_tf32(w1);
                } else {
                    bf[n][0] = __float_as_uint(w0); bf[n][1] = __float_as_uint(w1);
                }
            }
            #pragma unroll
            for (int m = 0; m < 4; m++)
                #pragma unroll
                for (int n = 0; n < 8; n++)
                    mma_tf32(acc[m][n], af[m], bf[n]);
        }

        buf++; if (buf >= NSTG) buf = 0;
    }

    // epilogue
    #pragma unroll
    for (int m = 0; m < 4; m++) {
        const int r0 = blockIdx.y * BM + warpRow * 64 + m * 16 + gid;
        const int r1 = r0 + 8;
        const float rs0 = rowscale ? rowscale[r0] : 1.0f;
        const float rs1 = rowscale ? rowscale[r1] : 1.0f;
        #pragma unroll
        for (int n = 0; n < 8; n++) {
            const int c0 = blockIdx.x * BN + warpCol * 64 + n * 8 + tig * 2;
            const float bv0 = bias ? bias[c0]     : 0.0f;
            const float bv1 = bias ? bias[c0 + 1] : 0.0f;
            float2 v0 = make_float2(acc[m][n][0] * rs0 + bv0, acc[m][n][1] * rs0 + bv1);
            float2 v1 = make_float2(acc[m][n][2] * rs1 + bv0, acc[m][n][3] * rs1 + bv1);
            *(float2*)&C[(size_t)r0 * Nn + c0] = v0;
            *(float2*)&C[(size_t)r1 * Nn + c0] = v1;
            if (C2) {
                float2 u0 = make_float2(__uint_as_float(rna_tf32(v0.x)),
                                        __uint_as_float(rna_tf32(v0.y)));
                float2 u1 = make_float2(__uint_as_float(rna_tf32(v1.x)),
                                        __uint_as_float(rna_tf32(v1.y)));
                *(float2*)&C2[(size_t)r0 * Nn + c0] = u0;
                *(float2*)&C2[(size_t)r1 * Nn + c0] = u1;
            }
        }
    }
}

// ---------------- per-node scores + exp factors (uses exact g_Wh) ----------------
__global__ void score_kernel(const float* __restrict__ a1, const float* __restrict__ a2,
                             const float* __restrict__ b1p, const float* __restrict__ b2p)
{
    const int warp = threadIdx.x >> 5;
    const int lane = threadIdx.x & 31;
    const int row  = blockIdx.x * 8 + warp;
    const float* w = g_Wh + (size_t)row * DOUT;

    float d1 = 0.0f, d2 = 0.0f;
    #pragma unroll
    for (int c = lane; c < DOUT; c += 32) {
        const float v = w[c];
        d1 += v * a1[c];
        d2 += v * a2[c];
    }
    #pragma unroll
    for (int o = 16; o > 0; o >>= 1) {
        d1 += __shfl_xor_sync(0xffffffffu, d1, o);
        d2 += __shfl_xor_sync(0xffffffffu, d2, o);
    }
    if (lane == 0) {
        const float v1 = d1 + b1p[0];
        const float v2 = d2 + b2p[0];
        g_s1[row] = v1;  g_s2[row] = v2;
        g_E1p[row] = expf(v1);         g_E1n[row] = expf(0.2f * v1);
        g_E2p[row] = expf(v2);         g_E2n[row] = expf(0.2f * v2);
    }
}

// ---------------- P generation (rna-rounded to tf32) + row-sum ----------------
__global__ void pgen_kernel(const int* __restrict__ adj)
{
    const int i = blockIdx.x;
    const int4*   arow = (const int4*)  (adj + (size_t)i * NN);
    float4*       prow = (float4*)      (g_P + (size_t)i * NN);
    const float4* s2v4 = (const float4*)g_s2;
    const float4* e2p4 = (const float4*)g_E2p;
    const float4* e2n4 = (const float4*)g_E2n;

    const float s1i = g_s1[i];
    const float e1p = g_E1p[i];
    const float e1n = g_E1n[i];

    float lsum = 0.0f;
    for (int j4 = threadIdx.x; j4 < NN / 4; j4 += 256) {
        const int4   a  = arow[j4];
        const float4 s2 = s2v4[j4];
        const float4 p2 = e2p4[j4];
        const float4 n2 = e2n4[j4];
        float4 o;
        o.x = (a.x > 0) ? ((s1i + s2.x > 0.0f) ? e1p * p2.x : e1n * n2.x) : 0.0f;
        o.y = (a.y > 0) ? ((s1i + s2.y > 0.0f) ? e1p * p2.y : e1n * n2.y) : 0.0f;
        o.z = (a.z > 0) ? ((s1i + s2.z > 0.0f) ? e1p * p2.z : e1n * n2.z) : 0.0f;
        o.w = (a.w > 0) ? ((s1i + s2.w > 0.0f) ? e1p * p2.w : e1n * n2.w) : 0.0f;
        // round to tf32 (rna) so GEMM2 can feed raw bits to the MMA
        o.x = __uint_as_float(rna_tf32(o.x));
        o.y = __uint_as_float(rna_tf32(o.y));
        o.z = __uint_as_float(rna_tf32(o.z));
        o.w = __uint_as_float(rna_tf32(o.w));
        lsum += (o.x + o.y) + (o.z + o.w);
        prow[j4] = o;
    }

    __shared__ float red[256];
    red[threadIdx.x] = lsum;
    __syncthreads();
    #pragma unroll
    for (int s = 128; s > 0; s >>= 1) {
        if (threadIdx.x < s) red[threadIdx.x] += red[threadIdx.x + s];
        __syncthreads();
    }
    if (threadIdx.x == 0) g_invZ[i] = 1.0f / red[0];
}

// ---------------- launch ----------------
extern "C" void kernel_launch(void* const* d_in, const int* in_sizes, int n_in,
                              void* d_out, int out_size)
{
    const float* h   = (const float*)d_in[0];
    const int*   adj = (const int*)  d_in[1];
    const float* W   = (const float*)d_in[2];
    const float* bW  = (const float*)d_in[3];
    const float* a1  = (const float*)d_in[4];
    const float* b1  = (const float*)d_in[5];
    const float* a2  = (const float*)d_in[6];
    const float* b2  = (const float*)d_in[7];
    float* out = (float*)d_out;

    cudaFuncSetAttribute(gemm_tf32_kernel<true>,
                         cudaFuncAttributeMaxDynamicSharedMemorySize, GEMM_SMEM_BYTES);
    cudaFuncSetAttribute(gemm_tf32_kernel<false>,
                         cudaFuncAttributeMaxDynamicSharedMemorySize, GEMM_SMEM_BYTES);

    void *pWh, *pWhR, *pP, *pInvZ;
    cudaGetSymbolAddress(&pWh,   g_Wh);
    cudaGetSymbolAddress(&pWhR,  g_WhR);
    cudaGetSymbolAddress(&pP,    g_P);
    cudaGetSymbolAddress(&pInvZ, g_invZ);

    // 1) Wh = h @ W + bW  (per-fragment rna cvt); also writes WhR = rna(Wh)
    {
        dim3 grid(DOUT / BN, NN / BM);
        gemm_tf32_kernel<true><<<grid, 256, GEMM_SMEM_BYTES>>>(
            h, W, (float*)pWh, (float*)pWhR, NN, DOUT, DIN, bW, nullptr);
    }

    // 2) scores s1,s2 and exp factors (exact Wh)
    score_kernel<<<NN / 8, 256>>>(a1, a2, b1, b2);

    // 3) P matrix (tf32-rounded) + 1/Z per row
    pgen_kernel<<<NN, 256>>>(adj);

    // 4) out = (P @ WhR) * invZ[row]  — raw-bit MMA on pre-rounded operands
    {
        dim3 grid(DOUT / BN, NN / BM);
        gemm_tf32_kernel<false><<<grid, 256, GEMM_SMEM_BYTES>>>(
            (const float*)pP, (const float*)pWhR, out, nullptr, NN, DOUT, NN, nullptr,
            (const float*)pInvZ);
    }
}

// round 15
// speedup vs baseline: 1.4327x; 1.0405x over previous
#include <cuda_runtime.h>
#include <cstdint>

#define NN   8192
#define DIN  512
#define DOUT 512

// ---------------- scratch (device globals; no allocation allowed) ----------------
__device__ __align__(256) float g_Wh[(size_t)NN * DOUT];    // 16 MB exact (for scores)
__device__ __align__(256) float g_WhR[(size_t)NN * DOUT];   // 16 MB rna-rounded to tf32
__device__ __align__(256) float g_P[(size_t)NN * NN];       // 268 MB (rna-rounded to tf32)
__device__ __align__(16) float g_s1[NN], g_s2[NN];
__device__ __align__(16) float g_E1p[NN], g_E1n[NN], g_E2p[NN], g_E2n[NN];
__device__ __align__(16) float g_invZ[NN];

// ---------------- helpers ----------------
__device__ __forceinline__ uint32_t rna_tf32(float x) {
    uint32_t r;
    asm("cvt.rna.tf32.f32 %0, %1;" : "=r"(r) : "f"(x));
    return r;
}

__device__ __forceinline__ void mma_tf32(float c[4], const uint32_t a[4], const uint32_t b[2]) {
    asm volatile(
        "mma.sync.aligned.m16n8k8.row.col.f32.tf32.tf32.f32 "
        "{%0,%1,%2,%3}, {%4,%5,%6,%7}, {%8,%9}, {%0,%1,%2,%3};\n"
        : "+f"(c[0]), "+f"(c[1]), "+f"(c[2]), "+f"(c[3])
        : "r"(a[0]), "r"(a[1]), "r"(a[2]), "r"(a[3]),
          "r"(b[0]), "r"(b[1]));
}

__device__ __forceinline__ void cp_async16(void* smem_ptr, const void* gmem_ptr) {
    uint32_t s = (uint32_t)__cvta_generic_to_shared(smem_ptr);
    asm volatile("cp.async.cg.shared.global [%0], [%1], 16;\n" :: "r"(s), "l"(gmem_ptr));
}
__device__ __forceinline__ void cp_async_commit() { asm volatile("cp.async.commit_group;\n"); }

// ---------------- GEMM: C[M,N] = A[M,K] @ B[K,N] (both row-major) ----------------
// BM=128, BN=128, BK=32; 128 threads = 4 warps as 2x2; warp tile 64x64.
// __launch_bounds__(128,2): TWO independent CTAs per SM — when one CTA is at its
// barrier / cp.async.wait, the other keeps the tensor pipe fed. Same 8 warps/SM
// and same 1.0 LDS-per-MMA ratio as the R13 config, but decoupled stalls.
// 3-stage cp.async pipeline, ONE __syncthreads per k-iter (valid with >=3 stages).
// DO_CVT=true : per-fragment cvt.rna (GEMM1, raw fp32 inputs)
// DO_CVT=false: raw bits into MMA — requires operands pre-rounded to tf32 (rna).
#define BM 128
#define BN 128
#define BK 32
#define NSTG 3
#define LDA_S 36    // BK+4  -> A fragment loads conflict-free
#define LDB_S 136   // BN+8  -> B fragment loads conflict-free
#define STG_FLOATS (BM * LDA_S + BK * LDB_S)              // 8960
#define GEMM_SMEM_BYTES (NSTG * STG_FLOATS * 4)           // 107520 (x2 CTAs = 215KB/SM)

template <bool DO_CVT>
__global__ void __launch_bounds__(128, 2)
gemm_tf32_kernel(const float* __restrict__ A, const float* __restrict__ B,
                 float* __restrict__ C, float* __restrict__ C2,
                 int M, int Nn, int K,
                 const float* __restrict__ bias, const float* __restrict__ rowscale)
{
    extern __shared__ float smem[];

    const int tid  = threadIdx.x;
    const int warp = tid >> 5;
    const int lane = tid & 31;
    const int warpRow = warp >> 1;   // 0..1  (64-row slice)
    const int warpCol = warp & 1;    // 0..1  (64-col slice)
    const int gid = lane >> 2;       // 0..7
    const int tig = lane & 3;        // 0..3

    const size_t aBase = (size_t)blockIdx.y * BM * (size_t)K;
    const size_t bBase = (size_t)blockIdx.x * BN;

    auto loadTile = [&](int kt, int buf) {
        float* As = smem + buf * STG_FLOATS;
        float* Bs = As + BM * LDA_S;
        const size_t k0 = (size_t)kt * BK;
        const float* Ag = A + aBase + k0;
        // A: 128 rows x 32 cols = 1024 float4 chunks, 8 per thread
        #pragma unroll
        for (int i = 0; i < 8; i++) {
            int idx = tid + i * 128;
            int r = idx >> 3, c = (idx & 7) * 4;
            cp_async16(&As[r * LDA_S + c], Ag + (size_t)r * K + c);
        }
        const float* Bg = B + k0 * (size_t)Nn + bBase;
        // B: 32 rows x 128 cols = 1024 float4 chunks, 8 per thread
        #pragma unroll
        for (int i = 0; i < 8; i++) {
            int idx = tid + i * 128;
            int r = idx >> 5, c = (idx & 31) * 4;
            cp_async16(&Bs[r * LDB_S + c], Bg + (size_t)r * Nn + c);
        }
        cp_async_commit();
    };

    float acc[4][8][4];
    #pragma unroll
    for (int m = 0; m < 4; m++)
        #pragma unroll
        for (int n = 0; n < 8; n++)
            #pragma unroll
            for (int q = 0; q < 4; q++)
                acc[m][n][q] = 0.0f;

    const int KT = K / BK;
    loadTile(0, 0);
    loadTile(1, 1);

    int buf = 0;
    for (int kt = 0; kt < KT; kt++) {
        if (kt + 1 < KT) asm volatile("cp.async.wait_group 1;\n" ::: "memory");
        else             asm volatile("cp.async.wait_group 0;\n" ::: "memory");
        __syncthreads();

        if (kt + 2 < KT) {
            int lb = buf + 2; if (lb >= NSTG) lb -= NSTG;
            loadTile(kt + 2, lb);
        }

        const float* Asb = smem + buf * STG_FLOATS;
        const float* Bsb = Asb + BM * LDA_S;
        const int rbase = warpRow * 64;
        const int cbase = warpCol * 64;

        #pragma unroll
        for (int s = 0; s < 4; s++) {
            const int kk = s * 8;
            uint32_t af[4][4];
            uint32_t bf[8][2];
            #pragma unroll
            for (int m = 0; m < 4; m++) {
                const int rb = rbase + m * 16;
                float v0 = Asb[(rb + gid)     * LDA_S + kk + tig];
                float v1 = Asb[(rb + gid + 8) * LDA_S + kk + tig];
                float v2 = Asb[(rb + gid)     * LDA_S + kk + tig + 4];
                float v3 = Asb[(rb + gid + 8) * LDA_S + kk + tig + 4];
                if (DO_CVT) {
                    af[m][0] = rna_tf32(v0); af[m][1] = rna_tf32(v1);
                    af[m][2] = rna_tf32(v2); af[m][3] = rna_tf32(v3);
                } else {
                    af[m][0] = __float_as_uint(v0); af[m][1] = __float_as_uint(v1);
                    af[m][2] = __float_as_uint(v2); af[m][3] = __float_as_uint(v3);
                }
            }
            #pragma unroll
            for (int n = 0; n < 8; n++) {
                const int cb = cbase + n * 8;
                float w0 = Bsb[(kk + tig)     * LDB_S + cb + gid];
                float w1 = Bsb[(kk + tig + 4) * LDB_S + cb + gid];
                if (DO_CVT) {
                    bf[n][0] = rna_tf32(w0); bf[n][1] = rna_tf32(w1);
                } else {
                    bf[n][0] = __float_as_uint(w0); bf[n][1] = __float_as_uint(w1);
                }
            }
            #pragma unroll
            for (int m = 0; m < 4; m++)
                #pragma unroll
                for (int n = 0; n < 8; n++)
                    mma_tf32(acc[m][n], af[m], bf[n]);
        }

        buf++; if (buf >= NSTG) buf = 0;
    }

    // epilogue
    #pragma unroll
    for (int m = 0; m < 4; m++) {
        const int r0 = blockIdx.y * BM + warpRow * 64 + m * 16 + gid;
        const int r1 = r0 + 8;
        const float rs0 = rowscale ? rowscale[r0] : 1.0f;
        const float rs1 = rowscale ? rowscale[r1] : 1.0f;
        #pragma unroll
        for (int n = 0; n < 8; n++) {
            const int c0 = blockIdx.x * BN + warpCol * 64 + n * 8 + tig * 2;
            const float bv0 = bias ? bias[c0]     : 0.0f;
            const float bv1 = bias ? bias[c0 + 1] : 0.0f;
            float2 v0 = make_float2(acc[m][n][0] * rs0 + bv0, acc[m][n][1] * rs0 + bv1);
            float2 v1 = make_float2(acc[m][n][2] * rs1 + bv0, acc[m][n][3] * rs1 + bv1);
            *(float2*)&C[(size_t)r0 * Nn + c0] = v0;
            *(float2*)&C[(size_t)r1 * Nn + c0] = v1;
            if (C2) {
                float2 u0 = make_float2(__uint_as_float(rna_tf32(v0.x)),
                                        __uint_as_float(rna_tf32(v0.y)));
                float2 u1 = make_float2(__uint_as_float(rna_tf32(v1.x)),
                                        __uint_as_float(rna_tf32(v1.y)));
                *(float2*)&C2[(size_t)r0 * Nn + c0] = u0;
                *(float2*)&C2[(size_t)r1 * Nn + c0] = u1;
            }
        }
    }
}

// ---------------- per-node scores + exp factors (uses exact g_Wh) ----------------
__global__ void score_kernel(const float* __restrict__ a1, const float* __restrict__ a2,
                             const float* __restrict__ b1p, const float* __restrict__ b2p)
{
    const int warp = threadIdx.x >> 5;
    const int lane = threadIdx.x & 31;
    const int row  = blockIdx.x * 8 + warp;
    const float* w = g_Wh + (size_t)row * DOUT;

    float d1 = 0.0f, d2 = 0.0f;
    #pragma unroll
    for (int c = lane; c < DOUT; c += 32) {
        const float v = w[c];
        d1 += v * a1[c];
        d2 += v * a2[c];
    }
    #pragma unroll
    for (int o = 16; o > 0; o >>= 1) {
        d1 += __shfl_xor_sync(0xffffffffu, d1, o);
        d2 += __shfl_xor_sync(0xffffffffu, d2, o);
    }
    if (lane == 0) {
        const float v1 = d1 + b1p[0];
        const float v2 = d2 + b2p[0];
        g_s1[row] = v1;  g_s2[row] = v2;
        g_E1p[row] = expf(v1);         g_E1n[row] = expf(0.2f * v1);
        g_E2p[row] = expf(v2);         g_E2n[row] = expf(0.2f * v2);
    }
}

// ---------------- P generation (rna-rounded to tf32) + row-sum ----------------
__global__ void pgen_kernel(const int* __restrict__ adj)
{
    const int i = blockIdx.x;
    const int4*   arow = (const int4*)  (adj + (size_t)i * NN);
    float4*       prow = (float4*)      (g_P + (size_t)i * NN);
    const float4* s2v4 = (const float4*)g_s2;
    const float4* e2p4 = (const float4*)g_E2p;
    const float4* e2n4 = (const float4*)g_E2n;

    const float s1i = g_s1[i];
    const float e1p = g_E1p[i];
    const float e1n = g_E1n[i];

    float lsum = 0.0f;
    for (int j4 = threadIdx.x; j4 < NN / 4; j4 += 256) {
        const int4   a  = arow[j4];
        const float4 s2 = s2v4[j4];
        const float4 p2 = e2p4[j4];
        const float4 n2 = e2n4[j4];
        float4 o;
        o.x = (a.x > 0) ? ((s1i + s2.x > 0.0f) ? e1p * p2.x : e1n * n2.x) : 0.0f;
        o.y = (a.y > 0) ? ((s1i + s2.y > 0.0f) ? e1p * p2.y : e1n * n2.y) : 0.0f;
        o.z = (a.z > 0) ? ((s1i + s2.z > 0.0f) ? e1p * p2.z : e1n * n2.z) : 0.0f;
        o.w = (a.w > 0) ? ((s1i + s2.w > 0.0f) ? e1p * p2.w : e1n * n2.w) : 0.0f;
        // round to tf32 (rna) so GEMM2 can feed raw bits to the MMA
        o.x = __uint_as_float(rna_tf32(o.x));
        o.y = __uint_as_float(rna_tf32(o.y));
        o.z = __uint_as_float(rna_tf32(o.z));
        o.w = __uint_as_float(rna_tf32(o.w));
        lsum += (o.x + o.y) + (o.z + o.w);
        prow[j4] = o;
    }

    __shared__ float red[256];
    red[threadIdx.x] = lsum;
    __syncthreads();
    #pragma unroll
    for (int s = 128; s > 0; s >>= 1) {
        if (threadIdx.x < s) red[threadIdx.x] += red[threadIdx.x + s];
        __syncthreads();
    }
    if (threadIdx.x == 0) g_invZ[i] = 1.0f / red[0];
}

// ---------------- launch ----------------
extern "C" void kernel_launch(void* const* d_in, const int* in_sizes, int n_in,
                              void* d_out, int out_size)
{
    const float* h   = (const float*)d_in[0];
    const int*   adj = (const int*)  d_in[1];
    const float* W   = (const float*)d_in[2];
    const float* bW  = (const float*)d_in[3];
    const float* a1  = (const float*)d_in[4];
    const float* b1  = (const float*)d_in[5];
    const float* a2  = (const float*)d_in[6];
    const float* b2  = (const float*)d_in[7];
    float* out = (float*)d_out;

    cudaFuncSetAttribute(gemm_tf32_kernel<true>,
                         cudaFuncAttributeMaxDynamicSharedMemorySize, GEMM_SMEM_BYTES);
    cudaFuncSetAttribute(gemm_tf32_kernel<false>,
                         cudaFuncAttributeMaxDynamicSharedMemorySize, GEMM_SMEM_BYTES);

    void *pWh, *pWhR, *pP, *pInvZ;
    cudaGetSymbolAddress(&pWh,   g_Wh);
    cudaGetSymbolAddress(&pWhR,  g_WhR);
    cudaGetSymbolAddress(&pP,    g_P);
    cudaGetSymbolAddress(&pInvZ, g_invZ);

    // 1) Wh = h @ W + bW  (per-fragment rna cvt); also writes WhR = rna(Wh)
    {
        dim3 grid(DOUT / BN, NN / BM);
        gemm_tf32_kernel<true><<<grid, 128, GEMM_SMEM_BYTES>>>(
            h, W, (float*)pWh, (float*)pWhR, NN, DOUT, DIN, bW, nullptr);
    }

    // 2) scores s1,s2 and exp factors (exact Wh)
    score_kernel<<<NN / 8, 256>>>(a1, a2, b1, b2);

    // 3) P matrix (tf32-rounded) + 1/Z per row
    pgen_kernel<<<NN, 256>>>(adj);

    // 4) out = (P @ WhR) * invZ[row]  — raw-bit MMA on pre-rounded operands
    {
        dim3 grid(DOUT / BN, NN / BM);
        gemm_tf32_kernel<false><<<grid, 128, GEMM_SMEM_BYTES>>>(
            (const float*)pP, (const float*)pWhR, out, nullptr, NN, DOUT, NN, nullptr,
            (const float*)pInvZ);
    }
}

// round 16
// speedup vs baseline: 2.2321x; 1.5579x over previous
#include <cuda_runtime.h>
#include <cuda_fp16.h>
#include <cstdint>

#define NN   8192
#define DIN  512
#define DOUT 512

// ---------------- scratch (device globals; no allocation allowed) ----------------
__device__ __align__(256) float  g_Wh[(size_t)NN * DOUT];    // 16 MB exact (for scores)
__device__ __align__(256) __half g_WhT[(size_t)DOUT * NN];   // 8 MB  fp16, transposed [feat][node]
__device__ __align__(256) __half g_Ph[(size_t)NN * NN];      // 134 MB fp16 P
__device__ __align__(16) float g_s1[NN], g_s2[NN];
__device__ __align__(16) float g_E1p[NN], g_E1n[NN], g_E2p[NN], g_E2n[NN];
__device__ __align__(16) float g_invZ[NN];

// ---------------- helpers ----------------
__device__ __forceinline__ uint32_t rna_tf32(float x) {
    uint32_t r;
    asm("cvt.rna.tf32.f32 %0, %1;" : "=r"(r) : "f"(x));
    return r;
}

__device__ __forceinline__ void mma_tf32(float c[4], const uint32_t a[4], const uint32_t b[2]) {
    asm volatile(
        "mma.sync.aligned.m16n8k8.row.col.f32.tf32.tf32.f32 "
        "{%0,%1,%2,%3}, {%4,%5,%6,%7}, {%8,%9}, {%0,%1,%2,%3};\n"
        : "+f"(c[0]), "+f"(c[1]), "+f"(c[2]), "+f"(c[3])
        : "r"(a[0]), "r"(a[1]), "r"(a[2]), "r"(a[3]),
          "r"(b[0]), "r"(b[1]));
}

__device__ __forceinline__ void mma_f16(float c[4], const uint32_t a[4], const uint32_t b[2]) {
    asm volatile(
        "mma.sync.aligned.m16n8k16.row.col.f32.f16.f16.f32 "
        "{%0,%1,%2,%3}, {%4,%5,%6,%7}, {%8,%9}, {%0,%1,%2,%3};\n"
        : "+f"(c[0]), "+f"(c[1]), "+f"(c[2]), "+f"(c[3])
        : "r"(a[0]), "r"(a[1]), "r"(a[2]), "r"(a[3]),
          "r"(b[0]), "r"(b[1]));
}

__device__ __forceinline__ void cp_async16(void* smem_ptr, const void* gmem_ptr) {
    uint32_t s = (uint32_t)__cvta_generic_to_shared(smem_ptr);
    asm volatile("cp.async.cg.shared.global [%0], [%1], 16;\n" :: "r"(s), "l"(gmem_ptr));
}
__device__ __forceinline__ void cp_async_commit() { asm volatile("cp.async.commit_group;\n"); }

// =================================================================================
// GEMM1 (tf32): C[M,N] = A[M,K] @ B[K,N], row-major both — exact R15 config.
// =================================================================================
#define BM 128
#define BN 128
#define BK 32
#define NSTG 3
#define LDA_S 36
#define LDB_S 136
#define STG_FLOATS (BM * LDA_S + BK * LDB_S)
#define GEMM_SMEM_BYTES (NSTG * STG_FLOATS * 4)   // 107520

__global__ void __launch_bounds__(128, 2)
gemm_tf32_kernel(const float* __restrict__ A, const float* __restrict__ B,
                 float* __restrict__ C, int M, int Nn, int K,
                 const float* __restrict__ bias)
{
    extern __shared__ float smem[];

    const int tid  = threadIdx.x;
    const int warp = tid >> 5;
    const int lane = tid & 31;
    const int warpRow = warp >> 1;
    const int warpCol = warp & 1;
    const int gid = lane >> 2;
    const int tig = lane & 3;

    const size_t aBase = (size_t)blockIdx.y * BM * (size_t)K;
    const size_t bBase = (size_t)blockIdx.x * BN;

    auto loadTile = [&](int kt, int buf) {
        float* As = smem + buf * STG_FLOATS;
        float* Bs = As + BM * LDA_S;
        const size_t k0 = (size_t)kt * BK;
        const float* Ag = A + aBase + k0;
        #pragma unroll
        for (int i = 0; i < 8; i++) {
            int idx = tid + i * 128;
            int r = idx >> 3, c = (idx & 7) * 4;
            cp_async16(&As[r * LDA_S + c], Ag + (size_t)r * K + c);
        }
        const float* Bg = B + k0 * (size_t)Nn + bBase;
        #pragma unroll
        for (int i = 0; i < 8; i++) {
            int idx = tid + i * 128;
            int r = idx >> 5, c = (idx & 31) * 4;
            cp_async16(&Bs[r * LDB_S + c], Bg + (size_t)r * Nn + c);
        }
        cp_async_commit();
    };

    float acc[4][8][4];
    #pragma unroll
    for (int m = 0; m < 4; m++)
        #pragma unroll
        for (int n = 0; n < 8; n++)
            #pragma unroll
            for (int q = 0; q < 4; q++)
                acc[m][n][q] = 0.0f;

    const int KT = K / BK;
    loadTile(0, 0);
    loadTile(1, 1);

    int buf = 0;
    for (int kt = 0; kt < KT; kt++) {
        if (kt + 1 < KT) asm volatile("cp.async.wait_group 1;\n" ::: "memory");
        else             asm volatile("cp.async.wait_group 0;\n" ::: "memory");
        __syncthreads();

        if (kt + 2 < KT) {
            int lb = buf + 2; if (lb >= NSTG) lb -= NSTG;
            loadTile(kt + 2, lb);
        }

        const float* Asb = smem + buf * STG_FLOATS;
        const float* Bsb = Asb + BM * LDA_S;
        const int rbase = warpRow * 64;
        const int cbase = warpCol * 64;

        #pragma unroll
        for (int s = 0; s < 4; s++) {
            const int kk = s * 8;
            uint32_t af[4][4];
            uint32_t bf[8][2];
            #pragma unroll
            for (int m = 0; m < 4; m++) {
                const int rb = rbase + m * 16;
                af[m][0] = rna_tf32(Asb[(rb + gid)     * LDA_S + kk + tig]);
                af[m][1] = rna_tf32(Asb[(rb + gid + 8) * LDA_S + kk + tig]);
                af[m][2] = rna_tf32(Asb[(rb + gid)     * LDA_S + kk + tig + 4]);
                af[m][3] = rna_tf32(Asb[(rb + gid + 8) * LDA_S + kk + tig + 4]);
            }
            #pragma unroll
            for (int n = 0; n < 8; n++) {
                const int cb = cbase + n * 8;
                bf[n][0] = rna_tf32(Bsb[(kk + tig)     * LDB_S + cb + gid]);
                bf[n][1] = rna_tf32(Bsb[(kk + tig + 4) * LDB_S + cb + gid]);
            }
            #pragma unroll
            for (int m = 0; m < 4; m++)
                #pragma unroll
                for (int n = 0; n < 8; n++)
                    mma_tf32(acc[m][n], af[m], bf[n]);
        }

        buf++; if (buf >= NSTG) buf = 0;
    }

    #pragma unroll
    for (int m = 0; m < 4; m++) {
        const int r0 = blockIdx.y * BM + warpRow * 64 + m * 16 + gid;
        const int r1 = r0 + 8;
        #pragma unroll
        for (int n = 0; n < 8; n++) {
            const int c0 = blockIdx.x * BN + warpCol * 64 + n * 8 + tig * 2;
            const float bv0 = bias ? bias[c0]     : 0.0f;
            const float bv1 = bias ? bias[c0 + 1] : 0.0f;
            float2 v0 = make_float2(acc[m][n][0] + bv0, acc[m][n][1] + bv1);
            float2 v1 = make_float2(acc[m][n][2] + bv0, acc[m][n][3] + bv1);
            *(float2*)&C[(size_t)r0 * Nn + c0] = v0;
            *(float2*)&C[(size_t)r1 * Nn + c0] = v1;
        }
    }
}

// =================================================================================
// GEMM2 (fp16 m16n8k16): C[M,N] = A_h[M,K] @ B_h^T where B_h is [N,K] k-contiguous.
// BM=128, BN=128, BK=64; 128 threads = 4 warps (2x2), warp tile 64x64; 2 CTAs/SM;
// 3-stage cp.async; one __syncthreads per k-iter. Half the MMA instructions and
// half the fragment LDS of the tf32 config per unit of work; half the k-iters.
// =================================================================================
#define FBM 128
#define FBN 128
#define FBK 64
#define FNSTG 3
#define FLD 72                                     // halves per smem row (64+8): conflict-free
#define FSTG_H (FBM * FLD + FBN * FLD)             // 18432 halves = 36864 B
#define FGEMM_SMEM_BYTES (FNSTG * FSTG_H * 2)      // 110592 (x2 CTAs = 221 KB/SM)

__global__ void __launch_bounds__(128, 2)
gemm_f16_kernel(const __half* __restrict__ A,   // [M][K] row-major
                const __half* __restrict__ B,   // [Ntotal][K] row-major (k-contiguous)
                float* __restrict__ C, int Nn, int K,
                const float* __restrict__ rowscale)
{
    extern __shared__ __half hsmem[];

    const int tid  = threadIdx.x;
    const int warp = tid >> 5;
    const int lane = tid & 31;
    const int warpRow = warp >> 1;   // 0..1
    const int warpCol = warp & 1;    // 0..1
    const int gid = lane >> 2;       // 0..7
    const int tig = lane & 3;        // 0..3

    const size_t aBase = (size_t)blockIdx.y * FBM * (size_t)K;
    const size_t bBase = (size_t)blockIdx.x * FBN * (size_t)K;

    auto loadTile = [&](int kt, int buf) {
        __half* As = hsmem + buf * FSTG_H;
        __half* Bs = As + FBM * FLD;
        const size_t k0 = (size_t)kt * FBK;
        const __half* Ag = A + aBase + k0;
        // A: 128 rows x 64 halves = 8 chunks(16B)/row -> 1024 chunks, 8/thread
        #pragma unroll
        for (int i = 0; i < 8; i++) {
            int idx = tid + i * 128;
            int r = idx >> 3, c = (idx & 7) * 8;   // halves
            cp_async16(&As[r * FLD + c], Ag + (size_t)r * K + c);
        }
        const __half* Bg = B + bBase + k0;
        #pragma unroll
        for (int i = 0; i < 8; i++) {
            int idx = tid + i * 128;
            int r = idx >> 3, c = (idx & 7) * 8;
            cp_async16(&Bs[r * FLD + c], Bg + (size_t)r * K + c);
        }
        cp_async_commit();
    };

    float acc[4][8][4];
    #pragma unroll
    for (int m = 0; m < 4; m++)
        #pragma unroll
        for (int n = 0; n < 8; n++)
            #pragma unroll
            for (int q = 0; q < 4; q++)
                acc[m][n][q] = 0.0f;

    const int KT = K / FBK;
    loadTile(0, 0);
    loadTile(1, 1);

    int buf = 0;
    for (int kt = 0; kt < KT; kt++) {
        if (kt + 1 < KT) asm volatile("cp.async.wait_group 1;\n" ::: "memory");
        else             asm volatile("cp.async.wait_group 0;\n" ::: "memory");
        __syncthreads();

        if (kt + 2 < KT) {
            int lb = buf + 2; if (lb >= FNSTG) lb -= FNSTG;
            loadTile(kt + 2, lb);
        }

        const __half* Asb = hsmem + buf * FSTG_H;
        const __half* Bsb = Asb + FBM * FLD;
        const int rbase = warpRow * 64;
        const int cbase = warpCol * 64;

        #pragma unroll
        for (int s = 0; s < 4; s++) {           // 4 x k16 steps per BK=64
            const int kk = s * 16;              // halves
            uint32_t af[4][4];
            uint32_t bf[8][2];
            #pragma unroll
            for (int m = 0; m < 4; m++) {
                const int rb = rbase + m * 16;
                af[m][0] = *(const uint32_t*)&Asb[(rb + gid)     * FLD + kk + 2 * tig];
                af[m][1] = *(const uint32_t*)&Asb[(rb + gid + 8) * FLD + kk + 2 * tig];
                af[m][2] = *(const uint32_t*)&Asb[(rb + gid)     * FLD + kk + 2 * tig + 8];
                af[m][3] = *(const uint32_t*)&Asb[(rb + gid + 8) * FLD + kk + 2 * tig + 8];
            }
            #pragma unroll
            for (int n = 0; n < 8; n++) {
                const int cb = cbase + n * 8;
                bf[n][0] = *(const uint32_t*)&Bsb[(cb + gid) * FLD + kk + 2 * tig];
                bf[n][1] = *(const uint32_t*)&Bsb[(cb + gid) * FLD + kk + 2 * tig + 8];
            }
            #pragma unroll
            for (int m = 0; m < 4; m++)
                #pragma unroll
                for (int n = 0; n < 8; n++)
                    mma_f16(acc[m][n], af[m], bf[n]);
        }

        buf++; if (buf >= FNSTG) buf = 0;
    }

    #pragma unroll
    for (int m = 0; m < 4; m++) {
        const int r0 = blockIdx.y * FBM + warpRow * 64 + m * 16 + gid;
        const int r1 = r0 + 8;
        const float rs0 = rowscale[r0];
        const float rs1 = rowscale[r1];
        #pragma unroll
        for (int n = 0; n < 8; n++) {
            const int c0 = blockIdx.x * FBN + warpCol * 64 + n * 8 + tig * 2;
            float2 v0 = make_float2(acc[m][n][0] * rs0, acc[m][n][1] * rs0);
            float2 v1 = make_float2(acc[m][n][2] * rs1, acc[m][n][3] * rs1);
            *(float2*)&C[(size_t)r0 * Nn + c0] = v0;
            *(float2*)&C[(size_t)r1 * Nn + c0] = v1;
        }
    }
}

// ---------------- transpose + fp16 convert: out[c][r] = half(in[r][c]) ----------------
__global__ void transpose_h_kernel(const float* __restrict__ in, __half* __restrict__ out,
                                   int R, int Cc)
{
    __shared__ float t[32][33];
    const int c0 = blockIdx.x * 32, r0 = blockIdx.y * 32;
    const int x = threadIdx.x, y = threadIdx.y;
    #pragma unroll
    for (int i = 0; i < 32; i += 8)
        t[y + i][x] = in[(size_t)(r0 + y + i) * Cc + c0 + x];
    __syncthreads();
    #pragma unroll
    for (int i = 0; i < 32; i += 8)
        out[(size_t)(c0 + y + i) * R + r0 + x] = __float2half_rn(t[x][y + i]);
}

// ---------------- per-node scores + exp factors (uses exact g_Wh) ----------------
__global__ void score_kernel(const float* __restrict__ a1, const float* __restrict__ a2,
                             const float* __restrict__ b1p, const float* __restrict__ b2p)
{
    const int warp = threadIdx.x >> 5;
    const int lane = threadIdx.x & 31;
    const int row  = blockIdx.x * 8 + warp;
    const float* w = g_Wh + (size_t)row * DOUT;

    float d1 = 0.0f, d2 = 0.0f;
    #pragma unroll
    for (int c = lane; c < DOUT; c += 32) {
        const float v = w[c];
        d1 += v * a1[c];
        d2 += v * a2[c];
    }
    #pragma unroll
    for (int o = 16; o > 0; o >>= 1) {
        d1 += __shfl_xor_sync(0xffffffffu, d1, o);
        d2 += __shfl_xor_sync(0xffffffffu, d2, o);
    }
    if (lane == 0) {
        const float v1 = d1 + b1p[0];
        const float v2 = d2 + b2p[0];
        g_s1[row] = v1;  g_s2[row] = v2;
        g_E1p[row] = expf(v1);         g_E1n[row] = expf(0.2f * v1);
        g_E2p[row] = expf(v2);         g_E2n[row] = expf(0.2f * v2);
    }
}

// ---------------- P generation (fp16) + deterministic row-sum ----------------
// P[i][j] = adj ? (s1_i+s2_j > 0 ? e^{s1_i} e^{s2_j} : e^{0.2 s1_i} e^{0.2 s2_j}) : 0
// stored as fp16 (rn); Z sums the rounded values for consistency with the GEMM.
__global__ void pgen_kernel(const int* __restrict__ adj)
{
    const int i = blockIdx.x;
    const int4*   arow = (const int4*)  (adj + (size_t)i * NN);
    uint2*        prow = (uint2*)       (g_Ph + (size_t)i * NN);
    const float4* s2v4 = (const float4*)g_s2;
    const float4* e2p4 = (const float4*)g_E2p;
    const float4* e2n4 = (const float4*)g_E2n;

    const float s1i = g_s1[i];
    const float e1p = g_E1p[i];
    const float e1n = g_E1n[i];

    float lsum = 0.0f;
    for (int j4 = threadIdx.x; j4 < NN / 4; j4 += 256) {
        const int4   a  = arow[j4];
        const float4 s2 = s2v4[j4];
        const float4 p2 = e2p4[j4];
        const float4 n2 = e2n4[j4];
        float4 o;
        o.x = (a.x > 0) ? ((s1i + s2.x > 0.0f) ? e1p * p2.x : e1n * n2.x) : 0.0f;
        o.y = (a.y > 0) ? ((s1i + s2.y > 0.0f) ? e1p * p2.y : e1n * n2.y) : 0.0f;
        o.z = (a.z > 0) ? ((s1i + s2.z > 0.0f) ? e1p * p2.z : e1n * n2.z) : 0.0f;
        o.w = (a.w > 0) ? ((s1i + s2.w > 0.0f) ? e1p * p2.w : e1n * n2.w) : 0.0f;
        __half hx = __float2half_rn(o.x);
        __half hy = __float2half_rn(o.y);
        __half hz = __float2half_rn(o.z);
        __half hw = __float2half_rn(o.w);
        lsum += (__half2float(hx) + __half2float(hy))
              + (__half2float(hz) + __half2float(hw));
        __half2 lo = __halves2half2(hx, hy);
        __half2 hi = __halves2half2(hz, hw);
        uint2 pk;
        pk.x = *(const uint32_t*)&lo;
        pk.y = *(const uint32_t*)&hi;
        prow[j4] = pk;
    }

    __shared__ float red[256];
    red[threadIdx.x] = lsum;
    __syncthreads();
    #pragma unroll
    for (int s = 128; s > 0; s >>= 1) {
        if (threadIdx.x < s) red[threadIdx.x] += red[threadIdx.x + s];
        __syncthreads();
    }
    if (threadIdx.x == 0) g_invZ[i] = 1.0f / red[0];
}

// ---------------- launch ----------------
extern "C" void kernel_launch(void* const* d_in, const int* in_sizes, int n_in,
                              void* d_out, int out_size)
{
    const float* h   = (const float*)d_in[0];
    const int*   adj = (const int*)  d_in[1];
    const float* W   = (const float*)d_in[2];
    const float* bW  = (const float*)d_in[3];
    const float* a1  = (const float*)d_in[4];
    const float* b1  = (const float*)d_in[5];
    const float* a2  = (const float*)d_in[6];
    const float* b2  = (const float*)d_in[7];
    float* out = (float*)d_out;

    cudaFuncSetAttribute(gemm_tf32_kernel,
                         cudaFuncAttributeMaxDynamicSharedMemorySize, GEMM_SMEM_BYTES);
    cudaFuncSetAttribute(gemm_f16_kernel,
                         cudaFuncAttributeMaxDynamicSharedMemorySize, FGEMM_SMEM_BYTES);

    void *pWh, *pWhT, *pPh, *pInvZ;
    cudaGetSymbolAddress(&pWh,   g_Wh);
    cudaGetSymbolAddress(&pWhT,  g_WhT);
    cudaGetSymbolAddress(&pPh,   g_Ph);
    cudaGetSymbolAddress(&pInvZ, g_invZ);

    // 1) Wh = h @ W + bW   (tf32, exact-enough fp32 out)
    {
        dim3 grid(DOUT / BN, NN / BM);
        gemm_tf32_kernel<<<grid, 128, GEMM_SMEM_BYTES>>>(
            h, W, (float*)pWh, NN, DOUT, DIN, bW);
    }

    // 2) scores s1,s2 and exp factors (exact Wh)
    score_kernel<<<NN / 8, 256>>>(a1, a2, b1, b2);

    // 2b) WhT fp16 [feat][node] for k-contiguous B staging
    transpose_h_kernel<<<dim3(DOUT / 32, NN / 32), dim3(32, 8)>>>(
        (const float*)pWh, (__half*)pWhT, NN, DOUT);

    // 3) P fp16 + 1/Z per row
    pgen_kernel<<<NN, 256>>>(adj);

    // 4) out = (P_h @ Wh_h) * invZ[row]   fp16 MMA, fp32 accumulate
    {
        dim3 grid(DOUT / FBN, NN / FBM);
        gemm_f16_kernel<<<grid, 128, FGEMM_SMEM_BYTES>>>(
            (const __half*)pPh, (const __half*)pWhT, out, DOUT, NN,
            (const float*)pInvZ);
    }
}

// round 17
// speedup vs baseline: 2.2487x; 1.0074x over previous
#include <cuda_runtime.h>
#include <cuda_fp16.h>
#include <cstdint>

#define NN   8192
#define DIN  512
#define DOUT 512

// ---------------- scratch (device globals; no allocation allowed) ----------------
__device__ __align__(256) float  g_Wh[(size_t)NN * DOUT];    // 16 MB exact (for scores)
__device__ __align__(256) __half g_WhT[(size_t)DOUT * NN];   // 8 MB  fp16, transposed [feat][node]
__device__ __align__(256) __half g_Ph[(size_t)NN * NN];      // 134 MB fp16 P
__device__ __align__(16) float  g_s1[NN], g_s2[NN];
__device__ __align__(16) float  g_E1p[NN], g_E1n[NN];
__device__ __align__(16) __half2 g_E2h[NN];                  // (e^{s2}, e^{0.2 s2}) packed
__device__ __align__(16) float  g_invZ[NN];

// ---------------- helpers ----------------
__device__ __forceinline__ uint32_t rna_tf32(float x) {
    uint32_t r;
    asm("cvt.rna.tf32.f32 %0, %1;" : "=r"(r) : "f"(x));
    return r;
}

__device__ __forceinline__ void mma_tf32(float c[4], const uint32_t a[4], const uint32_t b[2]) {
    asm volatile(
        "mma.sync.aligned.m16n8k8.row.col.f32.tf32.tf32.f32 "
        "{%0,%1,%2,%3}, {%4,%5,%6,%7}, {%8,%9}, {%0,%1,%2,%3};\n"
        : "+f"(c[0]), "+f"(c[1]), "+f"(c[2]), "+f"(c[3])
        : "r"(a[0]), "r"(a[1]), "r"(a[2]), "r"(a[3]),
          "r"(b[0]), "r"(b[1]));
}

__device__ __forceinline__ void mma_f16(float c[4], const uint32_t a[4], const uint32_t b[2]) {
    asm volatile(
        "mma.sync.aligned.m16n8k16.row.col.f32.f16.f16.f32 "
        "{%0,%1,%2,%3}, {%4,%5,%6,%7}, {%8,%9}, {%0,%1,%2,%3};\n"
        : "+f"(c[0]), "+f"(c[1]), "+f"(c[2]), "+f"(c[3])
        : "r"(a[0]), "r"(a[1]), "r"(a[2]), "r"(a[3]),
          "r"(b[0]), "r"(b[1]));
}

__device__ __forceinline__ void ldsm_x4(uint32_t& r0, uint32_t& r1, uint32_t& r2, uint32_t& r3,
                                        uint32_t addr) {
    asm volatile("ldmatrix.sync.aligned.m8n8.x4.shared.b16 {%0,%1,%2,%3}, [%4];"
                 : "=r"(r0), "=r"(r1), "=r"(r2), "=r"(r3) : "r"(addr));
}

__device__ __forceinline__ void cp_async16(void* smem_ptr, const void* gmem_ptr) {
    uint32_t s = (uint32_t)__cvta_generic_to_shared(smem_ptr);
    asm volatile("cp.async.cg.shared.global [%0], [%1], 16;\n" :: "r"(s), "l"(gmem_ptr));
}
__device__ __forceinline__ void cp_async_commit() { asm volatile("cp.async.commit_group;\n"); }

// =================================================================================
// GEMM1 (tf32): C[M,N] = A[M,K] @ B[K,N], row-major both — proven R15 config.
// =================================================================================
#define BM 128
#define BN 128
#define BK 32
#define NSTG 3
#define LDA_S 36
#define LDB_S 136
#define STG_FLOATS (BM * LDA_S + BK * LDB_S)
#define GEMM_SMEM_BYTES (NSTG * STG_FLOATS * 4)   // 107520

__global__ void __launch_bounds__(128, 2)
gemm_tf32_kernel(const float* __restrict__ A, const float* __restrict__ B,
                 float* __restrict__ C, int M, int Nn, int K,
                 const float* __restrict__ bias)
{
    extern __shared__ float smem[];

    const int tid  = threadIdx.x;
    const int warp = tid >> 5;
    const int lane = tid & 31;
    const int warpRow = warp >> 1;
    const int warpCol = warp & 1;
    const int gid = lane >> 2;
    const int tig = lane & 3;

    const size_t aBase = (size_t)blockIdx.y * BM * (size_t)K;
    const size_t bBase = (size_t)blockIdx.x * BN;

    auto loadTile = [&](int kt, int buf) {
        float* As = smem + buf * STG_FLOATS;
        float* Bs = As + BM * LDA_S;
        const size_t k0 = (size_t)kt * BK;
        const float* Ag = A + aBase + k0;
        #pragma unroll
        for (int i = 0; i < 8; i++) {
            int idx = tid + i * 128;
            int r = idx >> 3, c = (idx & 7) * 4;
            cp_async16(&As[r * LDA_S + c], Ag + (size_t)r * K + c);
        }
        const float* Bg = B + k0 * (size_t)Nn + bBase;
        #pragma unroll
        for (int i = 0; i < 8; i++) {
            int idx = tid + i * 128;
            int r = idx >> 5, c = (idx & 31) * 4;
            cp_async16(&Bs[r * LDB_S + c], Bg + (size_t)r * Nn + c);
        }
        cp_async_commit();
    };

    float acc[4][8][4];
    #pragma unroll
    for (int m = 0; m < 4; m++)
        #pragma unroll
        for (int n = 0; n < 8; n++)
            #pragma unroll
            for (int q = 0; q < 4; q++)
                acc[m][n][q] = 0.0f;

    const int KT = K / BK;
    loadTile(0, 0);
    loadTile(1, 1);

    int buf = 0;
    for (int kt = 0; kt < KT; kt++) {
        if (kt + 1 < KT) asm volatile("cp.async.wait_group 1;\n" ::: "memory");
        else             asm volatile("cp.async.wait_group 0;\n" ::: "memory");
        __syncthreads();

        if (kt + 2 < KT) {
            int lb = buf + 2; if (lb >= NSTG) lb -= NSTG;
            loadTile(kt + 2, lb);
        }

        const float* Asb = smem + buf * STG_FLOATS;
        const float* Bsb = Asb + BM * LDA_S;
        const int rbase = warpRow * 64;
        const int cbase = warpCol * 64;

        #pragma unroll
        for (int s = 0; s < 4; s++) {
            const int kk = s * 8;
            uint32_t af[4][4];
            uint32_t bf[8][2];
            #pragma unroll
            for (int m = 0; m < 4; m++) {
                const int rb = rbase + m * 16;
                af[m][0] = rna_tf32(Asb[(rb + gid)     * LDA_S + kk + tig]);
                af[m][1] = rna_tf32(Asb[(rb + gid + 8) * LDA_S + kk + tig]);
                af[m][2] = rna_tf32(Asb[(rb + gid)     * LDA_S + kk + tig + 4]);
                af[m][3] = rna_tf32(Asb[(rb + gid + 8) * LDA_S + kk + tig + 4]);
            }
            #pragma unroll
            for (int n = 0; n < 8; n++) {
                const int cb = cbase + n * 8;
                bf[n][0] = rna_tf32(Bsb[(kk + tig)     * LDB_S + cb + gid]);
                bf[n][1] = rna_tf32(Bsb[(kk + tig + 4) * LDB_S + cb + gid]);
            }
            #pragma unroll
            for (int m = 0; m < 4; m++)
                #pragma unroll
                for (int n = 0; n < 8; n++)
                    mma_tf32(acc[m][n], af[m], bf[n]);
        }

        buf++; if (buf >= NSTG) buf = 0;
    }

    #pragma unroll
    for (int m = 0; m < 4; m++) {
        const int r0 = blockIdx.y * BM + warpRow * 64 + m * 16 + gid;
        const int r1 = r0 + 8;
        #pragma unroll
        for (int n = 0; n < 8; n++) {
            const int c0 = blockIdx.x * BN + warpCol * 64 + n * 8 + tig * 2;
            const float bv0 = bias ? bias[c0]     : 0.0f;
            const float bv1 = bias ? bias[c0 + 1] : 0.0f;
            float2 v0 = make_float2(acc[m][n][0] + bv0, acc[m][n][1] + bv1);
            float2 v1 = make_float2(acc[m][n][2] + bv0, acc[m][n][3] + bv1);
            *(float2*)&C[(size_t)r0 * Nn + c0] = v0;
            *(float2*)&C[(size_t)r1 * Nn + c0] = v1;
        }
    }
}

// =================================================================================
// GEMM2 (fp16 m16n8k16 + ldmatrix): C[M,N] = A_h[M,K] @ B_h^T, B_h [N,K] k-contig.
// BM=128, BN=128, BK=64; 128 threads (4 warps 2x2), warp tile 64x64; 2 CTAs/SM.
// Fragments via ldmatrix.x4: FLD=72 halves => row stride 144 B = 9*16 B, so each
// 8-lane LDSM phase covers banks 4r+c bijectively — conflict-free.
// =================================================================================
#define FBM 128
#define FBN 128
#define FBK 64
#define FNSTG 3
#define FLD 72
#define FSTG_H (FBM * FLD + FBN * FLD)             // 18432 halves
#define FGEMM_SMEM_BYTES (FNSTG * FSTG_H * 2)      // 110592 (x2 CTAs = 221 KB/SM)

__global__ void __launch_bounds__(128, 2)
gemm_f16_kernel(const __half* __restrict__ A,   // [M][K] row-major
                const __half* __restrict__ B,   // [Ntotal][K] row-major (k-contiguous)
                float* __restrict__ C, int Nn, int K,
                const float* __restrict__ rowscale)
{
    extern __shared__ __half hsmem[];

    const int tid  = threadIdx.x;
    const int warp = tid >> 5;
    const int lane = tid & 31;
    const int warpRow = warp >> 1;   // 0..1
    const int warpCol = warp & 1;    // 0..1
    const int gid = lane >> 2;
    const int tig = lane & 3;

    const size_t aBase = (size_t)blockIdx.y * FBM * (size_t)K;
    const size_t bBase = (size_t)blockIdx.x * FBN * (size_t)K;

    auto loadTile = [&](int kt, int buf) {
        __half* As = hsmem + buf * FSTG_H;
        __half* Bs = As + FBM * FLD;
        const size_t k0 = (size_t)kt * FBK;
        const __half* Ag = A + aBase + k0;
        #pragma unroll
        for (int i = 0; i < 8; i++) {
            int idx = tid + i * 128;
            int r = idx >> 3, c = (idx & 7) * 8;
            cp_async16(&As[r * FLD + c], Ag + (size_t)r * K + c);
        }
        const __half* Bg = B + bBase + k0;
        #pragma unroll
        for (int i = 0; i < 8; i++) {
            int idx = tid + i * 128;
            int r = idx >> 3, c = (idx & 7) * 8;
            cp_async16(&Bs[r * FLD + c], Bg + (size_t)r * K + c);
        }
        cp_async_commit();
    };

    float acc[4][8][4];
    #pragma unroll
    for (int m = 0; m < 4; m++)
        #pragma unroll
        for (int n = 0; n < 8; n++)
            #pragma unroll
            for (int q = 0; q < 4; q++)
                acc[m][n][q] = 0.0f;

    // ldmatrix per-lane address components (halves)
    const uint32_t smemBase = (uint32_t)__cvta_generic_to_shared(hsmem);
    const int rbase = warpRow * 64;
    const int cbase = warpCol * 64;
    // A: lanes 0-7 rows 0-7 @k, 8-15 rows 8-15 @k, 16-23 rows 0-7 @k+8, 24-31 rows 8-15 @k+8
    const int aRowL  = rbase + (lane & 15);
    const int aColL  = (lane >> 4) * 8;
    const uint32_t aOffH = (uint32_t)(aRowL * FLD + aColL);
    // B: mats = (n0-7 @k), (n0-7 @k+8), (n8-15 @k), (n8-15 @k+8)
    const int bRowL  = cbase + (lane & 7) + ((lane >> 4) << 3);
    const int bColL  = ((lane >> 3) & 1) * 8;
    const uint32_t bOffH = (uint32_t)(FBM * FLD + bRowL * FLD + bColL);

    const int KT = K / FBK;
    loadTile(0, 0);
    loadTile(1, 1);

    int buf = 0;
    for (int kt = 0; kt < KT; kt++) {
        if (kt + 1 < KT) asm volatile("cp.async.wait_group 1;\n" ::: "memory");
        else             asm volatile("cp.async.wait_group 0;\n" ::: "memory");
        __syncthreads();

        if (kt + 2 < KT) {
            int lb = buf + 2; if (lb >= FNSTG) lb -= FNSTG;
            loadTile(kt + 2, lb);
        }

        const uint32_t stgBase = smemBase + (uint32_t)(buf * FSTG_H) * 2u;
        const uint32_t aAddr0 = stgBase + aOffH * 2u;
        const uint32_t bAddr0 = stgBase + bOffH * 2u;

        #pragma unroll
        for (int s = 0; s < 4; s++) {           // 4 x k16 steps per BK=64
            const uint32_t kb = (uint32_t)(s * 16) * 2u;   // bytes
            uint32_t af[4][4];
            uint32_t bf[8][2];
            #pragma unroll
            for (int m = 0; m < 4; m++)
                ldsm_x4(af[m][0], af[m][1], af[m][2], af[m][3],
                        aAddr0 + (uint32_t)(m * 16 * FLD) * 2u + kb);
            #pragma unroll
            for (int n2 = 0; n2 < 4; n2++)
                ldsm_x4(bf[2 * n2][0], bf[2 * n2][1], bf[2 * n2 + 1][0], bf[2 * n2 + 1][1],
                        bAddr0 + (uint32_t)(n2 * 16 * FLD) * 2u + kb);
            #pragma unroll
            for (int m = 0; m < 4; m++)
                #pragma unroll
                for (int n = 0; n < 8; n++)
                    mma_f16(acc[m][n], af[m], bf[n]);
        }

        buf++; if (buf >= FNSTG) buf = 0;
    }

    #pragma unroll
    for (int m = 0; m < 4; m++) {
        const int r0 = blockIdx.y * FBM + warpRow * 64 + m * 16 + gid;
        const int r1 = r0 + 8;
        const float rs0 = rowscale[r0];
        const float rs1 = rowscale[r1];
        #pragma unroll
        for (int n = 0; n < 8; n++) {
            const int c0 = blockIdx.x * FBN + warpCol * 64 + n * 8 + tig * 2;
            float2 v0 = make_float2(acc[m][n][0] * rs0, acc[m][n][1] * rs0);
            float2 v1 = make_float2(acc[m][n][2] * rs1, acc[m][n][3] * rs1);
            *(float2*)&C[(size_t)r0 * Nn + c0] = v0;
            *(float2*)&C[(size_t)r1 * Nn + c0] = v1;
        }
    }
}

// ---------------- transpose + fp16 convert: out[c][r] = half(in[r][c]) ----------------
__global__ void transpose_h_kernel(const float* __restrict__ in, __half* __restrict__ out,
                                   int R, int Cc)
{
    __shared__ float t[32][33];
    const int c0 = blockIdx.x * 32, r0 = blockIdx.y * 32;
    const int x = threadIdx.x, y = threadIdx.y;
    #pragma unroll
    for (int i = 0; i < 32; i += 8)
        t[y + i][x] = in[(size_t)(r0 + y + i) * Cc + c0 + x];
    __syncthreads();
    #pragma unroll
    for (int i = 0; i < 32; i += 8)
        out[(size_t)(c0 + y + i) * R + r0 + x] = __float2half_rn(t[x][y + i]);
}

// ---------------- per-node scores + exp factors (uses exact g_Wh) ----------------
__global__ void score_kernel(const float* __restrict__ a1, const float* __restrict__ a2,
                             const float* __restrict__ b1p, const float* __restrict__ b2p)
{
    const int warp = threadIdx.x >> 5;
    const int lane = threadIdx.x & 31;
    const int row  = blockIdx.x * 8 + warp;
    const float* w = g_Wh + (size_t)row * DOUT;

    float d1 = 0.0f, d2 = 0.0f;
    #pragma unroll
    for (int c = lane; c < DOUT; c += 32) {
        const float v = w[c];
        d1 += v * a1[c];
        d2 += v * a2[c];
    }
    #pragma unroll
    for (int o = 16; o > 0; o >>= 1) {
        d1 += __shfl_xor_sync(0xffffffffu, d1, o);
        d2 += __shfl_xor_sync(0xffffffffu, d2, o);
    }
    if (lane == 0) {
        const float v1 = d1 + b1p[0];
        const float v2 = d2 + b2p[0];
        g_s1[row] = v1;  g_s2[row] = v2;
        g_E1p[row] = expf(v1);
        g_E1n[row] = expf(0.2f * v1);
        g_E2h[row] = __halves2half2(__float2half_rn(expf(v2)),
                                    __float2half_rn(expf(0.2f * v2)));
    }
}

// ---------------- P generation (fp16) + deterministic row-sum ----------------
// per-j data: s2 (fp32, branch compare) + packed half2 (e^{s2}, e^{0.2 s2}).
// L1 bytes per 4 columns: 16 (adj) + 16 (s2) + 16 (e2h) = 48 vs previous 64.
__global__ void pgen_kernel(const int* __restrict__ adj)
{
    const int i = blockIdx.x;
    const int4*   arow = (const int4*)  (adj + (size_t)i * NN);
    uint2*        prow = (uint2*)       (g_Ph + (size_t)i * NN);
    const float4* s2v4 = (const float4*)g_s2;
    const uint4*  e2v4 = (const uint4*) g_E2h;   // 4 x half2 per uint4

    const float s1i = g_s1[i];
    const float e1p = g_E1p[i];
    const float e1n = g_E1n[i];

    float lsum = 0.0f;
    for (int j4 = threadIdx.x; j4 < NN / 4; j4 += 256) {
        const int4   a  = arow[j4];
        const float4 s2 = s2v4[j4];
        const uint4  e2 = e2v4[j4];
        const __half2 e2x = *(const __half2*)&e2.x;
        const __half2 e2y = *(const __half2*)&e2.y;
        const __half2 e2z = *(const __half2*)&e2.z;
        const __half2 e2w = *(const __half2*)&e2.w;
        float4 o;
        o.x = (a.x > 0) ? ((s1i + s2.x > 0.0f) ? e1p * __low2float(e2x)
                                               : e1n * __high2float(e2x)) : 0.0f;
        o.y = (a.y > 0) ? ((s1i + s2.y > 0.0f) ? e1p * __low2float(e2y)
                                               : e1n * __high2float(e2y)) : 0.0f;
        o.z = (a.z > 0) ? ((s1i + s2.z > 0.0f) ? e1p * __low2float(e2z)
                                               : e1n * __high2float(e2z)) : 0.0f;
        o.w = (a.w > 0) ? ((s1i + s2.w > 0.0f) ? e1p * __low2float(e2w)
                                               : e1n * __high2float(e2w)) : 0.0f;
        __half hx = __float2half_rn(o.x);
        __half hy = __float2half_rn(o.y);
        __half hz = __float2half_rn(o.z);
        __half hw = __float2half_rn(o.w);
        lsum += (__half2float(hx) + __half2float(hy))
              + (__half2float(hz) + __half2float(hw));
        __half2 lo = __halves2half2(hx, hy);
        __half2 hi = __halves2half2(hz, hw);
        uint2 pk;
        pk.x = *(const uint32_t*)&lo;
        pk.y = *(const uint32_t*)&hi;
        prow[j4] = pk;
    }

    __shared__ float red[256];
    red[threadIdx.x] = lsum;
    __syncthreads();
    #pragma unroll
    for (int s = 128; s > 0; s >>= 1) {
        if (threadIdx.x < s) red[threadIdx.x] += red[threadIdx.x + s];
        __syncthreads();
    }
    if (threadIdx.x == 0) g_invZ[i] = 1.0f / red[0];
}

// ---------------- launch ----------------
extern "C" void kernel_launch(void* const* d_in, const int* in_sizes, int n_in,
                              void* d_out, int out_size)
{
    const float* h   = (const float*)d_in[0];
    const int*   adj = (const int*)  d_in[1];
    const float* W   = (const float*)d_in[2];
    const float* bW  = (const float*)d_in[3];
    const float* a1  = (const float*)d_in[4];
    const float* b1  = (const float*)d_in[5];
    const float* a2  = (const float*)d_in[6];
    const float* b2  = (const float*)d_in[7];
    float* out = (float*)d_out;

    cudaFuncSetAttribute(gemm_tf32_kernel,
                         cudaFuncAttributeMaxDynamicSharedMemorySize, GEMM_SMEM_BYTES);
    cudaFuncSetAttribute(gemm_f16_kernel,
                         cudaFuncAttributeMaxDynamicSharedMemorySize, FGEMM_SMEM_BYTES);

    void *pWh, *pWhT, *pPh, *pInvZ;
    cudaGetSymbolAddress(&pWh,   g_Wh);
    cudaGetSymbolAddress(&pWhT,  g_WhT);
    cudaGetSymbolAddress(&pPh,   g_Ph);
    cudaGetSymbolAddress(&pInvZ, g_invZ);

    // 1) Wh = h @ W + bW   (tf32, fp32 out)
    {
        dim3 grid(DOUT / BN, NN / BM);
        gemm_tf32_kernel<<<grid, 128, GEMM_SMEM_BYTES>>>(
            h, W, (float*)pWh, NN, DOUT, DIN, bW);
    }

    // 2) scores s1,s2 and exp factors (exact Wh)
    score_kernel<<<NN / 8, 256>>>(a1, a2, b1, b2);

    // 2b) WhT fp16 [feat][node] for k-contiguous B staging
    transpose_h_kernel<<<dim3(DOUT / 32, NN / 32), dim3(32, 8)>>>(
        (const float*)pWh, (__half*)pWhT, NN, DOUT);

    // 3) P fp16 + 1/Z per row
    pgen_kernel<<<NN, 256>>>(adj);

    // 4) out = (P_h @ Wh_h) * invZ[row]   fp16 MMA via ldmatrix, fp32 accumulate
    {
        dim3 grid(DOUT / FBN, NN / FBM);
        gemm_f16_kernel<<<grid, 128, FGEMM_SMEM_BYTES>>>(
            (const __half*)pPh, (const __half*)pWhT, out, DOUT, NN,
            (const float*)pInvZ);
    }
}